// round 5
// baseline (speedup 1.0000x reference)
#include <cuda_runtime.h>
#include <cuda_bf16.h>
#include <cstdint>

#define B_  32
#define C_  512
#define HW_ 4096
#define N_  80

// Scratch (__device__ globals per allocation rules)
__device__ float         g_logits[(size_t)B_ * N_ * HW_];
__device__ __nv_bfloat16 g_att_hi[(size_t)B_ * N_ * HW_];
__device__ __nv_bfloat16 g_att_lo[(size_t)B_ * N_ * HW_];

// ---------------------------------------------------------------------------
// helpers
// ---------------------------------------------------------------------------
__device__ __forceinline__ uint32_t smem_u32(const void* p) {
    uint32_t a;
    asm("{ .reg .u64 t; cvta.to.shared.u64 t, %1; cvt.u32.u64 %0, t; }" : "=r"(a) : "l"(p));
    return a;
}
__device__ __forceinline__ uint32_t swz(uint32_t off) { return off ^ ((off >> 3) & 0x70u); }
__device__ __forceinline__ void sts64(uint32_t addr, uint32_t v0, uint32_t v1) {
    asm volatile("st.shared.v2.b32 [%0], {%1,%2};" :: "r"(addr), "r"(v0), "r"(v1));
}
__device__ __forceinline__ uint32_t lds32(uint32_t addr) {
    uint32_t v;
    asm volatile("ld.shared.b32 %0, [%1];" : "=r"(v) : "r"(addr));
    return v;
}
__device__ __forceinline__ void ldmx4t(uint32_t* r, uint32_t addr) {
    asm volatile("ldmatrix.sync.aligned.m8n8.x4.trans.shared.b16 {%0,%1,%2,%3}, [%4];"
                 : "=r"(r[0]), "=r"(r[1]), "=r"(r[2]), "=r"(r[3]) : "r"(addr));
}
// D(f32) += A(bf16) * B(bf16), m16n8k16
__device__ __forceinline__ void mma16816(float* d, const uint32_t* a, const uint32_t* b) {
    asm volatile(
        "mma.sync.aligned.m16n8k16.row.col.f32.bf16.bf16.f32 "
        "{%0,%1,%2,%3}, {%4,%5,%6,%7}, {%8,%9}, {%0,%1,%2,%3};"
        : "+f"(d[0]), "+f"(d[1]), "+f"(d[2]), "+f"(d[3])
        : "r"(a[0]), "r"(a[1]), "r"(a[2]), "r"(a[3]), "r"(b[0]), "r"(b[1]));
}
// split two f32 -> packed bf16 hi pair / lo (residual) pair; low half = first value
__device__ __forceinline__ void split2(float f0, float f1, uint32_t& hi, uint32_t& lo) {
    asm("cvt.rn.bf16x2.f32 %0, %1, %2;" : "=r"(hi) : "f"(f1), "f"(f0));
    float h0 = __uint_as_float(hi << 16);
    float h1 = __uint_as_float(hi & 0xffff0000u);
    asm("cvt.rn.bf16x2.f32 %0, %1, %2;" : "=r"(lo) : "f"(f1 - h1), "f"(f0 - h0));
}

#define G1_STAGE 53248u
#define G2_STAGE 36864u

// ===========================================================================
// GEMM1: logits[b,n,h] = sum_c W[n,c] * feats[b,c,h]
//   CTA tile [n=80 x h=128], K-chunk 64. 640 threads = 20 warps (5 m x 4 hq),
//   warp tile m16 x n32. Stage: Whi@0(10240) Wlo@10240,
//   Fhi@20480 (two 64-h halves, 8192 each), Flo@36864.  Stage=53248, x2 buf.
// ===========================================================================
__global__ __launch_bounds__(640, 1) void gemm1_mma(const float* __restrict__ feats,
                                                    const float* __restrict__ W) {
    extern __shared__ __align__(1024) char smem[];
    const uint32_t sb = smem_u32(smem);
    const int tid = threadIdx.x, wid = tid >> 5, lane = tid & 31;
    const int g = lane >> 2, t = lane & 3;
    const int mw = wid % 5, hwq = wid / 5;   // m0 = mw*16 (n), h quarter = hwq*32
    const int m0 = mw * 16;
    const int b = blockIdx.y, hC = blockIdx.x * 128;

    const float* Fb = feats + (size_t)b * C_ * HW_;

    float acc[4][4];
#pragma unroll
    for (int i = 0; i < 4; i++)
#pragma unroll
        for (int j = 0; j < 4; j++) acc[i][j] = 0.0f;

    float4 wst[2], fst[4];

    auto ldg_tile = [&](int kb) {
        const int c0 = kb * 64;
#pragma unroll
        for (int it = 0; it < 2; it++) {                 // W: 1280 float4
            int p = tid + it * 640, n = p >> 4, cf = p & 15;
            wst[it] = *(const float4*)(W + n * C_ + c0 + cf * 4);
        }
#pragma unroll
        for (int it = 0; it < 4; it++) {                 // F: 2048 float4
            int p = tid + it * 640;
            if (p < 2048) {
                int c = p >> 5, hf = p & 31;
                fst[it] = *(const float4*)(Fb + (size_t)(c0 + c) * HW_ + hC + hf * 4);
            }
        }
    };
    auto sts_tile = [&](uint32_t buf) {
#pragma unroll
        for (int it = 0; it < 2; it++) {
            int p = tid + it * 640, n = p >> 4, cf = p & 15;
            uint32_t h0, l0, h1, l1;
            split2(wst[it].x, wst[it].y, h0, l0);
            split2(wst[it].z, wst[it].w, h1, l1);
            uint32_t off = swz((uint32_t)(n * 128 + cf * 8));
            sts64(buf + off, h0, h1);
            sts64(buf + 10240u + off, l0, l1);
        }
#pragma unroll
        for (int it = 0; it < 4; it++) {
            int p = tid + it * 640;
            if (p < 2048) {
                int c = p >> 5, hf = p & 31;
                uint32_t h0, l0, h1, l1;
                split2(fst[it].x, fst[it].y, h0, l0);
                split2(fst[it].z, fst[it].w, h1, l1);
                uint32_t half = (uint32_t)(hf >> 4) * 8192u;
                uint32_t off = swz((uint32_t)(c * 128 + (hf & 15) * 8));
                sts64(buf + 20480u + half + off, h0, h1);
                sts64(buf + 36864u + half + off, l0, l1);
            }
        }
    };
    auto compute = [&](uint32_t buf) {
        const uint32_t Wh = buf, Wl = buf + 10240u;
        const uint32_t half = (uint32_t)(hwq >> 1) * 8192u;
        const uint32_t Fh = buf + 20480u + half;
        const uint32_t Fl = buf + 36864u + half;
        const uint32_t hsub = (uint32_t)(hwq & 1) * 32u;
#pragma unroll
        for (int ks = 0; ks < 4; ks++) {
            uint32_t ah[4], al[4];
#pragma unroll
            for (int q = 0; q < 4; q++) {
                uint32_t off = swz((uint32_t)((m0 + g + (q & 1) * 8) * 128 +
                                              ks * 32 + t * 4 + (q >> 1) * 16));
                ah[q] = lds32(Wh + off);
                al[q] = lds32(Wl + off);
            }
#pragma unroll
            for (int np = 0; np < 2; np++) {
                uint32_t rh[4], rl[4];
                uint32_t row = (uint32_t)(ks * 16 + (lane & 15));
                uint32_t colb = (hsub + np * 16 + ((lane >> 4) << 3)) * 2;
                uint32_t off = swz(row * 128 + colb);
                ldmx4t(rh, Fh + off);
                ldmx4t(rl, Fl + off);
                mma16816(acc[2 * np],     ah, rh + 0);
                mma16816(acc[2 * np],     ah, rl + 0);
                mma16816(acc[2 * np],     al, rh + 0);
                mma16816(acc[2 * np + 1], ah, rh + 2);
                mma16816(acc[2 * np + 1], ah, rl + 2);
                mma16816(acc[2 * np + 1], al, rh + 2);
            }
        }
    };

    // single-sync software pipeline
    ldg_tile(0);
    sts_tile(sb);
    __syncthreads();
#pragma unroll 1
    for (int kb = 0; kb < 8; kb++) {
        if (kb + 1 < 8) ldg_tile(kb + 1);
        compute(sb + (uint32_t)(kb & 1) * G1_STAGE);
        if (kb + 1 < 8) {
            sts_tile(sb + (uint32_t)((kb + 1) & 1) * G1_STAGE);
            __syncthreads();
        }
    }

    // epilogue: frag f = 2*np + q8 covers h block hwq*32 + np*16 + q8*8
#pragma unroll
    for (int f = 0; f < 4; f++) {
        int np = f >> 1, q8 = f & 1;
        int h = hC + hwq * 32 + np * 16 + q8 * 8 + 2 * t;
        int n = m0 + g;
        *(float2*)(g_logits + (size_t)(b * N_ + n) * HW_ + h) =
            make_float2(acc[f][0], acc[f][1]);
        *(float2*)(g_logits + (size_t)(b * N_ + n + 8) * HW_ + h) =
            make_float2(acc[f][2], acc[f][3]);
    }
}

// ===========================================================================
// Softmax over HW, g_logits -> split bf16 att maps. grid B*N, block 256.
// ===========================================================================
__global__ __launch_bounds__(256) void softmax_split() {
    const size_t row = blockIdx.x;
    const float* rowp = g_logits + row * HW_;
    const int tid = threadIdx.x;
    __shared__ float sm[8];

    float4 v[4];
#pragma unroll
    for (int q = 0; q < 4; q++) v[q] = ((const float4*)rowp)[tid + q * 256];

    float mx = -3.0e38f;
#pragma unroll
    for (int q = 0; q < 4; q++)
        mx = fmaxf(mx, fmaxf(fmaxf(v[q].x, v[q].y), fmaxf(v[q].z, v[q].w)));
#pragma unroll
    for (int o = 16; o; o >>= 1) mx = fmaxf(mx, __shfl_xor_sync(0xffffffffu, mx, o));
    if ((tid & 31) == 0) sm[tid >> 5] = mx;
    __syncthreads();
    mx = sm[0];
#pragma unroll
    for (int w = 1; w < 8; w++) mx = fmaxf(mx, sm[w]);
    __syncthreads();

    float s = 0.0f;
#pragma unroll
    for (int q = 0; q < 4; q++) {
        v[q].x = expf(v[q].x - mx); v[q].y = expf(v[q].y - mx);
        v[q].z = expf(v[q].z - mx); v[q].w = expf(v[q].w - mx);
        s += (v[q].x + v[q].y) + (v[q].z + v[q].w);
    }
#pragma unroll
    for (int o = 16; o; o >>= 1) s += __shfl_xor_sync(0xffffffffu, s, o);
    if ((tid & 31) == 0) sm[tid >> 5] = s;
    __syncthreads();
    s = sm[0];
#pragma unroll
    for (int w = 1; w < 8; w++) s += sm[w];

    const float inv = 1.0f / s;
    uint32_t* hi_w = (uint32_t*)(g_att_hi + row * HW_);
    uint32_t* lo_w = (uint32_t*)(g_att_lo + row * HW_);
#pragma unroll
    for (int q = 0; q < 4; q++) {
        uint32_t h0, l0, h1, l1;
        split2(v[q].x * inv, v[q].y * inv, h0, l0);
        split2(v[q].z * inv, v[q].w * inv, h1, l1);
        int idx = (tid + q * 256) * 2;
        hi_w[idx] = h0; hi_w[idx + 1] = h1;
        lo_w[idx] = l0; lo_w[idx + 1] = l1;
    }
}

// ===========================================================================
// GEMM2: out[b,n,c] = sum_h att[b,n,h] * feats[b,c,h]
//   CTA tile [c=64 x n=80], K-chunk 64, grid (8 c-tiles, 32 b) = 256 CTAs,
//   256 threads = 8 warps (4 m x 2 n), 2 CTAs/SM -> whole grid 1 wave.
//   Stage: Fhi@0(8192) Flo@8192, Ahi@16384(10240) Alo@26624. Stage=36864.
// ===========================================================================
__global__ __launch_bounds__(256, 2) void gemm2_mma(const float* __restrict__ feats,
                                                    float* __restrict__ out) {
    extern __shared__ __align__(1024) char smem[];
    const uint32_t sb = smem_u32(smem);
    const int tid = threadIdx.x, wid = tid >> 5, lane = tid & 31;
    const int g = lane >> 2, t = lane & 3;
    const int mw = wid & 3, nw = wid >> 2;   // m0 = mw*16 (c), n0 = nw*40 (n)
    const int m0 = mw * 16, n0 = nw * 40;
    const int b = blockIdx.y, c0 = blockIdx.x * 64;

    const float* Fb = feats + (size_t)b * C_ * HW_;
    const __nv_bfloat16* AH = g_att_hi + (size_t)b * N_ * HW_;
    const __nv_bfloat16* AL = g_att_lo + (size_t)b * N_ * HW_;

    float acc[5][4];
#pragma unroll
    for (int j = 0; j < 5; j++)
#pragma unroll
        for (int k = 0; k < 4; k++) acc[j][k] = 0.0f;

    float4 fstg[4];
    uint2 ahst[5], alst[5];

    auto ldg_tile = [&](int kb) {
        const int hk = kb * 64;
#pragma unroll
        for (int it = 0; it < 4; it++) {                 // F: 1024 float4
            int p = tid + it * 256, c = p >> 4, hf = p & 15;
            fstg[it] = *(const float4*)(Fb + (size_t)(c0 + c) * HW_ + hk + hf * 4);
        }
#pragma unroll
        for (int it = 0; it < 5; it++) {                 // att: 1280 uint2 each
            int p = tid + it * 256, n = p >> 4, w2 = p & 15;
            ahst[it] = ((const uint2*)(AH + (size_t)n * HW_ + hk))[w2];
            alst[it] = ((const uint2*)(AL + (size_t)n * HW_ + hk))[w2];
        }
    };
    auto sts_tile = [&](uint32_t buf) {
#pragma unroll
        for (int it = 0; it < 4; it++) {
            int p = tid + it * 256, c = p >> 4, hf = p & 15;
            uint32_t h0, l0, h1, l1;
            split2(fstg[it].x, fstg[it].y, h0, l0);
            split2(fstg[it].z, fstg[it].w, h1, l1);
            uint32_t off = swz((uint32_t)(c * 128 + hf * 8));
            sts64(buf + off, h0, h1);
            sts64(buf + 8192u + off, l0, l1);
        }
#pragma unroll
        for (int it = 0; it < 5; it++) {
            int p = tid + it * 256, n = p >> 4, w2 = p & 15;
            uint32_t off = swz((uint32_t)(n * 128 + w2 * 8));
            sts64(buf + 16384u + off, ahst[it].x, ahst[it].y);
            sts64(buf + 26624u + off, alst[it].x, alst[it].y);
        }
    };
    auto compute = [&](uint32_t buf) {
        const uint32_t Fh = buf, Fl = buf + 8192u;
        const uint32_t Bh = buf + 16384u, Bl = buf + 26624u;
#pragma unroll
        for (int ks = 0; ks < 4; ks++) {
            uint32_t ah[4], al[4];
#pragma unroll
            for (int q = 0; q < 4; q++) {
                uint32_t off = swz((uint32_t)((m0 + g + (q & 1) * 8) * 128 +
                                              ks * 32 + t * 4 + (q >> 1) * 16));
                ah[q] = lds32(Fh + off);
                al[q] = lds32(Fl + off);
            }
#pragma unroll
            for (int nf = 0; nf < 5; nf++) {
                uint32_t bh[2], bl[2];
#pragma unroll
                for (int q = 0; q < 2; q++) {
                    uint32_t off = swz((uint32_t)((n0 + nf * 8 + g) * 128 +
                                                  ks * 32 + t * 4 + q * 16));
                    bh[q] = lds32(Bh + off);
                    bl[q] = lds32(Bl + off);
                }
                mma16816(acc[nf], ah, bh);
                mma16816(acc[nf], ah, bl);
                mma16816(acc[nf], al, bh);
            }
        }
    };

    ldg_tile(0);
    sts_tile(sb);
    __syncthreads();
#pragma unroll 1
    for (int kb = 0; kb < 64; kb++) {
        if (kb + 1 < 64) ldg_tile(kb + 1);
        compute(sb + (uint32_t)(kb & 1) * G2_STAGE);
        if (kb + 1 < 64) {
            sts_tile(sb + (uint32_t)((kb + 1) & 1) * G2_STAGE);
            __syncthreads();
        }
    }

    // epilogue: out[b, n, c]
    {
        int c = c0 + m0 + g;
#pragma unroll
        for (int nf = 0; nf < 5; nf++) {
            int n = n0 + nf * 8 + 2 * t;
            float* p = out + ((size_t)b * N_ + n) * C_ + c;
            p[0]      = acc[nf][0];
            p[C_]     = acc[nf][1];
            p[8]      = acc[nf][2];
            p[C_ + 8] = acc[nf][3];
        }
    }
}

// ---------------------------------------------------------------------------
#define G1_SMEM (2 * 53248)
#define G2_SMEM (2 * 36864)

extern "C" void kernel_launch(void* const* d_in, const int* in_sizes, int n_in,
                              void* d_out, int out_size) {
    const float* feats = (const float*)d_in[0];  // [32, 512, 4096]
    const float* W     = (const float*)d_in[1];  // [80, 512]
    float* out         = (float*)d_out;          // [32, 80, 512]

    cudaFuncSetAttribute(gemm1_mma, cudaFuncAttributeMaxDynamicSharedMemorySize, G1_SMEM);
    cudaFuncSetAttribute(gemm2_mma, cudaFuncAttributeMaxDynamicSharedMemorySize, G2_SMEM);

    gemm1_mma<<<dim3(HW_ / 128, B_), 640, G1_SMEM>>>(feats, W);
    softmax_split<<<B_ * N_, 256>>>();
    gemm2_mma<<<dim3(8, B_), 256, G2_SMEM>>>(feats, out);
}

// round 6
// speedup vs baseline: 1.0962x; 1.0962x over previous
#include <cuda_runtime.h>
#include <cuda_bf16.h>
#include <cstdint>

#define B_  32
#define C_  512
#define HW_ 4096
#define N_  80

// Scratch (__device__ globals per allocation rules)
__device__ float         g_logits[(size_t)B_ * N_ * HW_];
__device__ __nv_bfloat16 g_att_hi[(size_t)B_ * N_ * HW_];
__device__ __nv_bfloat16 g_att_lo[(size_t)B_ * N_ * HW_];
__device__ __nv_bfloat16 g_f_hi[(size_t)B_ * C_ * HW_];   // feats split, written by gemm1
__device__ __nv_bfloat16 g_f_lo[(size_t)B_ * C_ * HW_];
__device__ uint32_t      g_w_hi[N_ * C_ / 2];             // W split (packed bf16x2)
__device__ uint32_t      g_w_lo[N_ * C_ / 2];

// ---------------------------------------------------------------------------
// helpers
// ---------------------------------------------------------------------------
__device__ __forceinline__ uint32_t smem_u32(const void* p) {
    uint32_t a;
    asm("{ .reg .u64 t; cvta.to.shared.u64 t, %1; cvt.u32.u64 %0, t; }" : "=r"(a) : "l"(p));
    return a;
}
__device__ __forceinline__ uint32_t swz(uint32_t off) { return off ^ ((off >> 3) & 0x70u); }
__device__ __forceinline__ void sts64(uint32_t addr, uint32_t v0, uint32_t v1) {
    asm volatile("st.shared.v2.b32 [%0], {%1,%2};" :: "r"(addr), "r"(v0), "r"(v1));
}
#define CP_ASYNC16(dst, src) \
    asm volatile("cp.async.cg.shared.global [%0], [%1], 16;" :: "r"(dst), "l"(src))
#define CP_COMMIT() asm volatile("cp.async.commit_group;" ::: "memory")
#define CP_WAIT0()  asm volatile("cp.async.wait_group 0;" ::: "memory")

__device__ __forceinline__ void ldmx4(uint32_t* r, uint32_t addr) {       // non-trans
    asm volatile("ldmatrix.sync.aligned.m8n8.x4.shared.b16 {%0,%1,%2,%3}, [%4];"
                 : "=r"(r[0]), "=r"(r[1]), "=r"(r[2]), "=r"(r[3]) : "r"(addr));
}
__device__ __forceinline__ void ldmx2(uint32_t* r, uint32_t addr) {       // non-trans
    asm volatile("ldmatrix.sync.aligned.m8n8.x2.shared.b16 {%0,%1}, [%2];"
                 : "=r"(r[0]), "=r"(r[1]) : "r"(addr));
}
__device__ __forceinline__ void ldmx4t(uint32_t* r, uint32_t addr) {      // trans
    asm volatile("ldmatrix.sync.aligned.m8n8.x4.trans.shared.b16 {%0,%1,%2,%3}, [%4];"
                 : "=r"(r[0]), "=r"(r[1]), "=r"(r[2]), "=r"(r[3]) : "r"(addr));
}
// D(f32) += A(bf16) * B(bf16), m16n8k16
__device__ __forceinline__ void mma16816(float* d, const uint32_t* a,
                                         uint32_t b0, uint32_t b1) {
    asm volatile(
        "mma.sync.aligned.m16n8k16.row.col.f32.bf16.bf16.f32 "
        "{%0,%1,%2,%3}, {%4,%5,%6,%7}, {%8,%9}, {%0,%1,%2,%3};"
        : "+f"(d[0]), "+f"(d[1]), "+f"(d[2]), "+f"(d[3])
        : "r"(a[0]), "r"(a[1]), "r"(a[2]), "r"(a[3]), "r"(b0), "r"(b1));
}
// split two f32 -> packed bf16 hi pair / lo (residual) pair; low half = first value
__device__ __forceinline__ void split2(float f0, float f1, uint32_t& hi, uint32_t& lo) {
    asm("cvt.rn.bf16x2.f32 %0, %1, %2;" : "=r"(hi) : "f"(f1), "f"(f0));
    float h0 = __uint_as_float(hi << 16);
    float h1 = __uint_as_float(hi & 0xffff0000u);
    asm("cvt.rn.bf16x2.f32 %0, %1, %2;" : "=r"(lo) : "f"(f1 - h1), "f"(f0 - h0));
}

#define G1_STAGE 53248u
#define G2_STAGE 53248u

// ===========================================================================
// split_w: W f32 [80,512] -> g_w_hi/lo packed bf16x2. grid 80, block 256.
// ===========================================================================
__global__ void split_w(const float* __restrict__ W) {
    int i = blockIdx.x * 256 + threadIdx.x;          // 20480 float2 units
    float2 v = ((const float2*)W)[i];
    uint32_t hi, lo; split2(v.x, v.y, hi, lo);
    g_w_hi[i] = hi; g_w_lo[i] = lo;
}

// ===========================================================================
// GEMM1: logits[b,n,h] = sum_c W[n,c] * feats[b,c,h]; also writes split feats.
//   CTA tile [n=80 x h=128], K-chunk 64. 640 threads = 20 warps (5 m x 4 hq),
//   warp tile m16 x n32. Stage: Wh@0(10240) Wl@10240,
//   Fh@20480 (two 64-h halves, 8192 each), Fl@36864. Stage=53248, x2 buf.
// ===========================================================================
__global__ __launch_bounds__(640, 1) void gemm1_mma(const float* __restrict__ feats) {
    extern __shared__ __align__(1024) char smem[];
    const uint32_t sb = smem_u32(smem);
    const int tid = threadIdx.x, wid = tid >> 5, lane = tid & 31;
    const int g = lane >> 2, t = lane & 3;
    const int mw = wid % 5, hwq = wid / 5;   // m0 = mw*16 (n), h quarter = hwq*32
    const int m0 = mw * 16;
    const int b = blockIdx.y, hC = blockIdx.x * 128;

    const float* Fb = feats + (size_t)b * C_ * HW_;

    float acc[4][4];
#pragma unroll
    for (int i = 0; i < 4; i++)
#pragma unroll
        for (int j = 0; j < 4; j++) acc[i][j] = 0.0f;

    float4 fst[4];

    auto cp_w = [&](uint32_t buf, int kb) {
        const int c0b = kb * 128;                      // byte offset within W row
#pragma unroll
        for (int it = 0; it < 2; it++) {
            int p = tid + it * 640;                    // 1280 = 2 x 640 chunks
            int sel = p >= 640;
            int q = sel ? p - 640 : p;
            int n = q >> 3, cb = (q & 7) * 16;
            const char* src = (sel ? (const char*)g_w_lo : (const char*)g_w_hi) +
                              n * 1024 + c0b + cb;
            CP_ASYNC16(buf + (sel ? 10240u : 0u) + swz((uint32_t)(n * 128 + cb)), src);
        }
    };
    auto ldg_f = [&](int kb) {
        const int c0 = kb * 64;
#pragma unroll
        for (int it = 0; it < 4; it++) {               // 2048 float4
            int p = tid + it * 640;
            if (p < 2048) {
                int c = p >> 5, hf = p & 31;
                fst[it] = *(const float4*)(Fb + (size_t)(c0 + c) * HW_ + hC + hf * 4);
            }
        }
    };
    auto sts_stg_f = [&](uint32_t buf, int kb) {
        const int c0 = kb * 64;
#pragma unroll
        for (int it = 0; it < 4; it++) {
            int p = tid + it * 640;
            if (p < 2048) {
                int c = p >> 5, hf = p & 31;
                uint32_t h0, l0, h1, l1;
                split2(fst[it].x, fst[it].y, h0, l0);
                split2(fst[it].z, fst[it].w, h1, l1);
                uint32_t half = (uint32_t)(hf >> 4) * 8192u;
                uint32_t off = swz((uint32_t)(c * 128 + (hf & 15) * 8));
                sts64(buf + 20480u + half + off, h0, h1);
                sts64(buf + 36864u + half + off, l0, l1);
                size_t gi = ((size_t)(b * C_ + c0 + c) * HW_ + hC + hf * 4);
                *(uint2*)((char*)g_f_hi + gi * 2) = make_uint2(h0, h1);
                *(uint2*)((char*)g_f_lo + gi * 2) = make_uint2(l0, l1);
            }
        }
    };
    auto compute = [&](uint32_t buf) {
        const uint32_t Wh = buf, Wl = buf + 10240u;
        const uint32_t half = (uint32_t)(hwq >> 1) * 8192u;
        const uint32_t Fh = buf + 20480u + half;
        const uint32_t Fl = buf + 36864u + half;
        const uint32_t hsub = (uint32_t)(hwq & 1) * 32u;
        const uint32_t arow = (uint32_t)(m0 + (lane & 15)) * 128;
#pragma unroll
        for (int ks = 0; ks < 4; ks++) {
            uint32_t ah[4], al[4];
            uint32_t aoff = swz(arow + ks * 32 + (lane >> 4) * 16);
            ldmx4(ah, Wh + aoff);
            ldmx4(al, Wl + aoff);
#pragma unroll
            for (int np = 0; np < 2; np++) {
                uint32_t rh[4], rl[4];
                uint32_t boff = swz((uint32_t)(ks * 16 + (lane & 15)) * 128 +
                                    (hsub + np * 16 + ((lane >> 4) << 3)) * 2);
                ldmx4t(rh, Fh + boff);
                ldmx4t(rl, Fl + boff);
                mma16816(acc[2 * np],     ah, rh[0], rh[1]);
                mma16816(acc[2 * np],     ah, rl[0], rl[1]);
                mma16816(acc[2 * np],     al, rh[0], rh[1]);
                mma16816(acc[2 * np + 1], ah, rh[2], rh[3]);
                mma16816(acc[2 * np + 1], ah, rl[2], rl[3]);
                mma16816(acc[2 * np + 1], al, rh[2], rh[3]);
            }
        }
    };

    // pipeline: one sync per iteration
    cp_w(sb, 0); CP_COMMIT();
    ldg_f(0);
    sts_stg_f(sb, 0);
    CP_WAIT0();
    __syncthreads();
#pragma unroll 1
    for (int kb = 0; kb < 8; kb++) {
        const uint32_t cur = sb + (uint32_t)(kb & 1) * G1_STAGE;
        const uint32_t nxt = sb + (uint32_t)((kb + 1) & 1) * G1_STAGE;
        if (kb + 1 < 8) { cp_w(nxt, kb + 1); CP_COMMIT(); ldg_f(kb + 1); }
        compute(cur);
        if (kb + 1 < 8) {
            sts_stg_f(nxt, kb + 1);
            CP_WAIT0();
            __syncthreads();
        }
    }

    // epilogue: frag f = 2*np + q8 covers h block hwq*32 + np*16 + q8*8
#pragma unroll
    for (int f = 0; f < 4; f++) {
        int np = f >> 1, q8 = f & 1;
        int h = hC + hwq * 32 + np * 16 + q8 * 8 + 2 * t;
        int n = m0 + g;
        *(float2*)(g_logits + (size_t)(b * N_ + n) * HW_ + h) =
            make_float2(acc[f][0], acc[f][1]);
        *(float2*)(g_logits + (size_t)(b * N_ + n + 8) * HW_ + h) =
            make_float2(acc[f][2], acc[f][3]);
    }
}

// ===========================================================================
// Softmax over HW, g_logits -> split bf16 att maps. grid B*N, block 256.
// ===========================================================================
__global__ __launch_bounds__(256) void softmax_split() {
    const size_t row = blockIdx.x;
    const float* rowp = g_logits + row * HW_;
    const int tid = threadIdx.x;
    __shared__ float sm[8];

    float4 v[4];
#pragma unroll
    for (int q = 0; q < 4; q++) v[q] = ((const float4*)rowp)[tid + q * 256];

    float mx = -3.0e38f;
#pragma unroll
    for (int q = 0; q < 4; q++)
        mx = fmaxf(mx, fmaxf(fmaxf(v[q].x, v[q].y), fmaxf(v[q].z, v[q].w)));
#pragma unroll
    for (int o = 16; o; o >>= 1) mx = fmaxf(mx, __shfl_xor_sync(0xffffffffu, mx, o));
    if ((tid & 31) == 0) sm[tid >> 5] = mx;
    __syncthreads();
    mx = sm[0];
#pragma unroll
    for (int w = 1; w < 8; w++) mx = fmaxf(mx, sm[w]);
    __syncthreads();

    float s = 0.0f;
#pragma unroll
    for (int q = 0; q < 4; q++) {
        v[q].x = expf(v[q].x - mx); v[q].y = expf(v[q].y - mx);
        v[q].z = expf(v[q].z - mx); v[q].w = expf(v[q].w - mx);
        s += (v[q].x + v[q].y) + (v[q].z + v[q].w);
    }
#pragma unroll
    for (int o = 16; o; o >>= 1) s += __shfl_xor_sync(0xffffffffu, s, o);
    if ((tid & 31) == 0) sm[tid >> 5] = s;
    __syncthreads();
    s = sm[0];
#pragma unroll
    for (int w = 1; w < 8; w++) s += sm[w];

    const float inv = 1.0f / s;
    uint32_t* hi_w = (uint32_t*)(g_att_hi + row * HW_);
    uint32_t* lo_w = (uint32_t*)(g_att_lo + row * HW_);
#pragma unroll
    for (int q = 0; q < 4; q++) {
        uint32_t h0, l0, h1, l1;
        split2(v[q].x * inv, v[q].y * inv, h0, l0);
        split2(v[q].z * inv, v[q].w * inv, h1, l1);
        int idx = (tid + q * 256) * 2;
        hi_w[idx] = h0; hi_w[idx + 1] = h1;
        lo_w[idx] = l0; lo_w[idx + 1] = l1;
    }
}

// ===========================================================================
// GEMM2: out[b,n,c] = sum_h att[b,n,h] * feats[b,c,h]   (all bf16 pre-split)
//   CTA tile [c=128 x n=80], K-chunk 64, grid (4, 32) = 128 CTAs (1 wave),
//   512 threads = 16 warps (8 m x 2 n), warp tile m16 x n40.
//   Stage: Fh@0(16384) Fl@16384, Ah@32768(10240) Al@43008. Stage=53248, x2.
//   All staging via cp.async (bf16), fragments via ldmatrix.
// ===========================================================================
__global__ __launch_bounds__(512, 1) void gemm2_mma(float* __restrict__ out) {
    extern __shared__ __align__(1024) char smem[];
    const uint32_t sb = smem_u32(smem);
    const int tid = threadIdx.x, wid = tid >> 5, lane = tid & 31;
    const int g = lane >> 2, t = lane & 3;
    const int mw = wid & 7, nw = wid >> 3;   // m0 = mw*16 (c), n0 = nw*40 (n)
    const int m0 = mw * 16, n0 = nw * 40;
    const int b = blockIdx.y, c0 = blockIdx.x * 128;

    const char* FHb = (const char*)g_f_hi + ((size_t)(b * C_ + c0) * HW_) * 2;
    const char* FLb = (const char*)g_f_lo + ((size_t)(b * C_ + c0) * HW_) * 2;
    const char* AHb = (const char*)g_att_hi + ((size_t)b * N_ * HW_) * 2;
    const char* ALb = (const char*)g_att_lo + ((size_t)b * N_ * HW_) * 2;

    float acc[5][4];
#pragma unroll
    for (int j = 0; j < 5; j++)
#pragma unroll
        for (int k = 0; k < 4; k++) acc[j][k] = 0.0f;

    auto cp_tile = [&](uint32_t buf, int kb) {
        const int hkb = kb * 128;                      // byte offset along h
#pragma unroll
        for (int it = 0; it < 7; it++) {
            int p = tid + it * 512;                    // 3328 chunks of 16B
            if (p < 3328) {
                uint32_t dst; const char* src;
                if (p < 2048) {                        // F: 1024 hi + 1024 lo
                    int sel = p >> 10, q = p & 1023;
                    int c = q >> 3, cb = (q & 7) * 16;
                    src = (sel ? FLb : FHb) + (size_t)c * (HW_ * 2) + hkb + cb;
                    dst = buf + (uint32_t)sel * 16384u + swz((uint32_t)(c * 128 + cb));
                } else {                               // att: 640 hi + 640 lo
                    int q = p - 2048;
                    int sel = q >= 640;
                    int r = sel ? q - 640 : q;
                    int n = r >> 3, cb = (r & 7) * 16;
                    src = (sel ? ALb : AHb) + (size_t)n * (HW_ * 2) + hkb + cb;
                    dst = buf + 32768u + (uint32_t)sel * 10240u +
                          swz((uint32_t)(n * 128 + cb));
                }
                CP_ASYNC16(dst, src);
            }
        }
    };
    auto compute = [&](uint32_t buf) {
        const uint32_t Fh = buf, Fl = buf + 16384u;
        const uint32_t Bh = buf + 32768u, Bl = buf + 43008u;
        const uint32_t arow = (uint32_t)(m0 + (lane & 15)) * 128;
#pragma unroll
        for (int ks = 0; ks < 4; ks++) {
            const uint32_t kc = ks * 32 + (lane >> 4) * 16;
            uint32_t ah[4], al[4];
            uint32_t aoff = swz(arow + kc);
            ldmx4(ah, Fh + aoff);
            ldmx4(al, Fl + aoff);
            // B: two x4 loads (n16 blocks) + one x2 (last n8), hi & lo
            uint32_t bh[2][4], bl[2][4], bh2[2], bl2[2];
#pragma unroll
            for (int j = 0; j < 2; j++) {
                uint32_t boff = swz((uint32_t)(n0 + j * 16 + (lane & 15)) * 128 + kc);
                ldmx4(bh[j], Bh + boff);
                ldmx4(bl[j], Bl + boff);
            }
            {
                uint32_t boff = swz((uint32_t)(n0 + 32 + (lane & 7)) * 128 +
                                    ks * 32 + ((lane >> 3) & 1) * 16);
                ldmx2(bh2, Bh + boff);
                ldmx2(bl2, Bl + boff);
            }
#pragma unroll
            for (int j = 0; j < 2; j++) {
                // nf = 2j : mats {0,2};  nf = 2j+1 : mats {1,3}
                mma16816(acc[2 * j],     ah, bh[j][0], bh[j][2]);
                mma16816(acc[2 * j],     ah, bl[j][0], bl[j][2]);
                mma16816(acc[2 * j],     al, bh[j][0], bh[j][2]);
                mma16816(acc[2 * j + 1], ah, bh[j][1], bh[j][3]);
                mma16816(acc[2 * j + 1], ah, bl[j][1], bl[j][3]);
                mma16816(acc[2 * j + 1], al, bh[j][1], bh[j][3]);
            }
            mma16816(acc[4], ah, bh2[0], bh2[1]);
            mma16816(acc[4], ah, bl2[0], bl2[1]);
            mma16816(acc[4], al, bh2[0], bh2[1]);
        }
    };

    cp_tile(sb, 0); CP_COMMIT();
    CP_WAIT0();
    __syncthreads();
#pragma unroll 1
    for (int kb = 0; kb < 64; kb++) {
        const uint32_t cur = sb + (uint32_t)(kb & 1) * G2_STAGE;
        const uint32_t nxt = sb + (uint32_t)((kb + 1) & 1) * G2_STAGE;
        if (kb + 1 < 64) { cp_tile(nxt, kb + 1); CP_COMMIT(); }
        compute(cur);
        if (kb + 1 < 64) {
            CP_WAIT0();
            __syncthreads();
        }
    }

    // epilogue: out[b, n, c]
    {
        int c = c0 + m0 + g;
#pragma unroll
        for (int nf = 0; nf < 5; nf++) {
            int n = n0 + nf * 8 + 2 * t;
            float* p = out + ((size_t)b * N_ + n) * C_ + c;
            p[0]      = acc[nf][0];
            p[C_]     = acc[nf][1];
            p[8]      = acc[nf][2];
            p[C_ + 8] = acc[nf][3];
        }
    }
}

// ---------------------------------------------------------------------------
#define G1_SMEM (2 * 53248)
#define G2_SMEM (2 * 53248)

extern "C" void kernel_launch(void* const* d_in, const int* in_sizes, int n_in,
                              void* d_out, int out_size) {
    const float* feats = (const float*)d_in[0];  // [32, 512, 4096]
    const float* W     = (const float*)d_in[1];  // [80, 512]
    float* out         = (float*)d_out;          // [32, 80, 512]

    cudaFuncSetAttribute(gemm1_mma, cudaFuncAttributeMaxDynamicSharedMemorySize, G1_SMEM);
    cudaFuncSetAttribute(gemm2_mma, cudaFuncAttributeMaxDynamicSharedMemorySize, G2_SMEM);

    split_w<<<80, 256>>>(W);
    gemm1_mma<<<dim3(HW_ / 128, B_), 640, G1_SMEM>>>(feats);
    softmax_split<<<B_ * N_, 256>>>();
    gemm2_mma<<<dim3(4, B_), 512, G2_SMEM>>>(out);
}